// round 17
// baseline (speedup 1.0000x reference)
#include <cuda_runtime.h>
#include <cuda_fp16.h>
#include <cstdint>

#define T_STEPS 512
#define BATCH   512
#define FEAT    128
#define HID     512
#define TAGS    2
#define NG      2048          // 4*HID
#define K1      640           // FEAT + HID
#define K2      1024          // HID + HID
#define NCTA    128
#define MT      128
#define NT      64
#define NTHREADS 512          // 16 warps: 8 M-subgroups x 2 N-halves, tile 16x32
#define NTGROUP 32            // CTAs per M-group

// resident weights: per k64 block = 64 rows(N) x 128B = 8192 B
#define W1_BLKS 8             // h1 part only (orig k-blocks 2..9)
#define W2_BLKS 16
#define SM_W1   0
#define SM_W2   (W1_BLKS * 8192)                  // 65536
#define SM_AST  ((W1_BLKS + W2_BLKS) * 8192)      // 196608
#define SMEM_BYTES (SM_AST + 16 * 2 * 1024)       // 229376: 16 warps x 2 k32 slots

// gemm_x kernel smem
#define GX_W    0                                  // 2 blocks = 16384
#define GX_AST  16384
#define GX_SMEM (16384 + 16 * 2 * 1024)            // 49152

// ------------------------- device globals (scratch) -------------------------
__device__ __half g_Wp1h[NG * K1];       // permuted [n][k], fp16
__device__ __half g_Wp2h[NG * K2];
__device__ float  g_b1[NG];
__device__ float  g_b2[NG];
__device__ __half g_sigh[T_STEPS * BATCH * FEAT];
__device__ __half g_h1[2][BATCH * HID];
__device__ __half g_h2[2][BATCH * HID];
__device__ float  g_c1[BATCH * HID];
__device__ float  g_c2[BATCH * HID];
__device__ unsigned g_bar4[4];
__device__ unsigned g_gen4[4];
// precomputed x*W1x^T in per-thread fragment order: [ct][t][tid][16 halves]
__device__ __half g_gx[(size_t)NCTA * T_STEPS * NTHREADS * 16];

// ------------------------------- helpers ------------------------------------
__device__ __forceinline__ float sigm(float x) { return 1.0f / (1.0f + __expf(-x)); }
__device__ __forceinline__ void cp16(uint32_t dst, const void* src) {
    asm volatile("cp.async.cg.shared.global [%0], [%1], 16;\n" :: "r"(dst), "l"(src));
}
#define CPA_COMMIT() asm volatile("cp.async.commit_group;\n")
#define CPA_WAIT1()  asm volatile("cp.async.wait_group 1;\n")
#define CPA_WAIT0()  asm volatile("cp.async.wait_group 0;\n")
#define LDSM4(r0, r1, r2, r3, addr)                                            \
    asm volatile("ldmatrix.sync.aligned.m8n8.x4.shared.b16 {%0,%1,%2,%3}, [%4];" \
        : "=r"(r0), "=r"(r1), "=r"(r2), "=r"(r3) : "r"(addr))

__device__ __forceinline__ unsigned ld_acq(const unsigned* p) {
    unsigned v;
    asm volatile("ld.acquire.gpu.u32 %0, [%1];" : "=r"(v) : "l"(p) : "memory");
    return v;
}

// permuted column index n -> original gate row (gate-interleave of 8)
__device__ __forceinline__ int orig_row(long n) {
    int chunk = (int)(n >> 5), w = (int)(n & 31);
    int q = w >> 3, r = w & 7;
    return q * HID + chunk * 8 + r;
}

// ------------------------------ prep kernel ---------------------------------
__global__ void prep_kernel(const float* __restrict__ signal,
                            const float* __restrict__ Wih1, const float* __restrict__ Whh1,
                            const float* __restrict__ bih1, const float* __restrict__ bhh1,
                            const float* __restrict__ Wih2, const float* __restrict__ Whh2,
                            const float* __restrict__ bih2, const float* __restrict__ bhh2) {
    const long NW1 = (long)NG * K1;
    const long NW2 = (long)NG * K2;
    const long NSIG = (long)T_STEPS * BATCH * FEAT;
    const long NH   = (long)BATCH * HID;
    const long TOT = NW1 + NW2 + 2L * NG + NSIG + 6L * NH;
    for (long i = blockIdx.x * (long)blockDim.x + threadIdx.x; i < TOT;
         i += (long)gridDim.x * blockDim.x) {
        if (i < NW1) {
            long n = i / K1, k = i % K1;
            int o = orig_row(n);
            float v = (k < FEAT) ? Wih1[(long)o * FEAT + k]
                                 : Whh1[(long)o * HID + (k - FEAT)];
            g_Wp1h[i] = __float2half_rn(v);
        } else if (i < NW1 + NW2) {
            long j = i - NW1;
            long n = j / K2, k = j % K2;
            int o = orig_row(n);
            float v = (k < HID) ? Wih2[(long)o * HID + k]
                                : Whh2[(long)o * HID + (k - HID)];
            g_Wp2h[j] = __float2half_rn(v);
        } else if (i < NW1 + NW2 + NG) {
            long n = i - NW1 - NW2;
            int o = orig_row(n);
            g_b1[n] = bih1[o] + bhh1[o];
        } else if (i < NW1 + NW2 + 2L * NG) {
            long n = i - NW1 - NW2 - NG;
            int o = orig_row(n);
            g_b2[n] = bih2[o] + bhh2[o];
        } else if (i < NW1 + NW2 + 2L * NG + NSIG) {
            long j = i - NW1 - NW2 - 2L * NG;
            g_sigh[j] = __float2half_rn(signal[j]);
        } else {
            long j = i - (NW1 + NW2 + 2L * NG + NSIG);
            long seg = j / NH, o = j % NH;
            if      (seg == 0) g_h1[0][o] = __float2half_rn(0.f);
            else if (seg == 1) g_h1[1][o] = __float2half_rn(0.f);
            else if (seg == 2) g_h2[0][o] = __float2half_rn(0.f);
            else if (seg == 3) g_h2[1][o] = __float2half_rn(0.f);
            else if (seg == 4) g_c1[o]    = 0.f;
            else               g_c2[o]    = 0.f;
        }
    }
    if (blockIdx.x == 0 && threadIdx.x < 4) {
        g_bar4[threadIdx.x] = 0u;
        g_gen4[threadIdx.x] = 0u;
    }
}

// --------------------- per-M-group barrier (32 CTAs) -------------------------
__device__ __forceinline__ void group_sync(int mt, unsigned target) {
    __syncthreads();
    if (threadIdx.x == 0) {
        __threadfence();
        unsigned a = atomicAdd(&g_bar4[mt], 1u);
        if (a == NTGROUP - 1u) {
            atomicExch(&g_bar4[mt], 0u);
            __threadfence();
            atomicAdd(&g_gen4[mt], 1u);
        } else {
            while (ld_acq(&g_gen4[mt]) < target) { }
        }
        __threadfence();
    }
    __syncthreads();
}

// --------------------------- warp-private A staging (k32) --------------------
struct Src {
    const __half* a0; int lda0; int split;   // k32 chunk idx < split -> a0
    const __half* a1; int lda1;              // otherwise a1
};

// one warp fills its own 1KB slot (16 rows x 64B); lane: row=lane>>1, 32B half
__device__ __forceinline__ void issue_sub(const Src& s, int idx, int rowA, int coff,
                                          uint32_t d0, uint32_t d1) {
    const __half* p;
    if (idx < s.split) p = s.a0 + (size_t)rowA * s.lda0 + idx * 32 + coff;
    else               p = s.a1 + (size_t)rowA * s.lda1 + (idx - s.split) * 32 + coff;
    cp16(d0, p);
    cp16(d1, p + 8);
    CPA_COMMIT();
}

// ---------------------- k32 chunk MMA (B resident in smem) -------------------
__device__ __forceinline__ void mma_sub(uint32_t stg, const uint32_t a_off[2],
                                        uint32_t wphase, int k16g,
                                        const uint32_t bo_sw[2][4], float acc[4][4]) {
    #pragma unroll
    for (int kk = 0; kk < 2; kk++) {
        unsigned a0, a1, a2, a3;
        LDSM4(a0, a1, a2, a3, stg + a_off[kk]);
        const int kg = k16g + kk;
        const uint32_t wblk = wphase + (uint32_t)(kg >> 2) * 8192u;
        const int k4 = kg & 3;
        unsigned b[2][4];
        #pragma unroll
        for (int p2 = 0; p2 < 2; p2++)
            LDSM4(b[p2][0], b[p2][1], b[p2][2], b[p2][3], wblk + bo_sw[p2][k4]);
        #pragma unroll
        for (int j = 0; j < 4; j++) {
            const int p2 = j >> 1, hi = (j & 1) * 2;
            asm volatile(
                "mma.sync.aligned.m16n8k16.row.col.f32.f16.f16.f32 "
                "{%0,%1,%2,%3}, {%4,%5,%6,%7}, {%8,%9}, {%0,%1,%2,%3};\n"
                : "+f"(acc[j][0]), "+f"(acc[j][1]),
                  "+f"(acc[j][2]), "+f"(acc[j][3])
                : "r"(a0), "r"(a1), "r"(a2), "r"(a3),
                  "r"(b[p2][hi]), "r"(b[p2][hi + 1]));
        }
    }
}

__device__ __forceinline__ void zero_acc(float acc[4][4]) {
    #pragma unroll
    for (int j = 0; j < 4; j++)
        #pragma unroll
        for (int r = 0; r < 4; r++) acc[j][r] = 0.f;
}

// ------------- register-local LSTM epilogue (c preloaded in regs) -----------
__device__ __forceinline__ void epilogue(const float acc[4][4],
                                         const float br[4][2],
                                         const float2 cv[2],
                                         float* __restrict__ cbuf,
                                         __half* __restrict__ hout,
                                         int base_row, int colb) {
    #pragma unroll
    for (int rp = 0; rp < 2; rp++) {
        const int row = base_row + rp * 8;
        float2 c2 = cv[rp];
        float hv[2];
        #pragma unroll
        for (int b = 0; b < 2; b++) {
            const int rg = rp * 2 + b;
            float gi = acc[0][rg] + br[0][b];
            float gf = acc[1][rg] + br[1][b];
            float gg = acc[2][rg] + br[2][b];
            float go = acc[3][rg] + br[3][b];
            float c  = b ? c2.y : c2.x;
            float cn = sigm(gf) * c + sigm(gi) * tanhf(gg);
            if (b) c2.y = cn; else c2.x = cn;
            hv[b] = sigm(go) * tanhf(cn);
        }
        *(float2*)(cbuf + (size_t)row * HID + colb) = c2;
        *(__half2*)(hout + (size_t)row * HID + colb) =
            __floats2half2_rn(hv[0], hv[1]);
    }
}

// ----------------------------- output projection -----------------------------
__device__ __forceinline__ void out_calc(int tp, const __half* __restrict__ h2cur,
                                         const float* __restrict__ Wlin,
                                         const float* __restrict__ blin,
                                         float* __restrict__ out, int ct) {
    const int tid = threadIdx.x, lane = tid & 31, wid = tid >> 5;
    if (wid >= 4) return;
    const int b = ct * 4 + wid;
    const __half* hrow = h2cur + (size_t)b * HID;
    float s0 = 0.f, s1 = 0.f;
    #pragma unroll 8
    for (int k = lane; k < HID; k += 32) {
        float hv = __half2float(__ldcg(hrow + k));
        s0 += hv * __ldg(Wlin + k);
        s1 += hv * __ldg(Wlin + HID + k);
    }
    #pragma unroll
    for (int o = 16; o; o >>= 1) {
        s0 += __shfl_xor_sync(0xffffffffu, s0, o);
        s1 += __shfl_xor_sync(0xffffffffu, s1, o);
    }
    if (lane == 0) {
        out[(size_t)b * (T_STEPS * TAGS) + tp * TAGS + 0] = s0 + blin[0];
        out[(size_t)b * (T_STEPS * TAGS) + tp * TAGS + 1] = s1 + blin[1];
    }
}

// ======================= gemm_x: gx = x_t * W1x^T for all t ==================
__global__ void __launch_bounds__(NTHREADS, 1)
gemm_x_kernel() {
    extern __shared__ char smc[];
    const uint32_t smu = (uint32_t)__cvta_generic_to_shared(smc);
    const int tid = threadIdx.x, w = tid >> 5, lane = tid & 31;
    const int mg = w >> 1, nh = w & 1;
    const int ct = blockIdx.x;
    const int mt = ct >> 5, nt = ct & 31;
    const int m0 = mt * MT, n0 = nt * NT;

    // preload W1x (k blocks 0,1 of g_Wp1h): 512 threads, 1 cp16 each per block
    {
        int row = tid >> 3, part = tid & 7;
        uint32_t o = (uint32_t)(row * 128 + part * 16);
        o ^= ((uint32_t)(row & 7)) << 4;
        const __half* s1 = g_Wp1h + (size_t)(n0 + row) * K1 + part * 8;
        cp16(smu + GX_W + o, s1);
        cp16(smu + GX_W + 8192 + o, s1 + 64);
        CPA_COMMIT();
        CPA_WAIT0();
        __syncthreads();
    }

    const uint32_t b_off0 = (uint32_t)(((((lane >> 4) & 1) * 8 + (lane & 7)) * 128)
                                       + ((lane >> 3) & 1) * 16);
    uint32_t bo_sw[2][4];
    #pragma unroll
    for (int p2 = 0; p2 < 2; p2++)
        #pragma unroll
        for (int kk = 0; kk < 4; kk++) {
            uint32_t bo = b_off0 + (uint32_t)((2 * nh + p2) * 2048 + kk * 32);
            bo ^= (bo >> 3) & 0x70u;
            bo_sw[p2][kk] = bo;
        }

    // warp-private A stage: 2 slots x 1KB (R9 layout)
    const uint32_t awbase = smu + GX_AST + (uint32_t)w * 2048u;
    const uint32_t wpre = (uint32_t)((lane >> 2) * 128 + ((lane >> 1) & 1) * 64
                                     + (lane & 1) * 32);
    const uint32_t wsw  = ((uint32_t)(lane >> 2) & 7u) << 4;
    const uint32_t wd0  = wpre ^ wsw;
    const uint32_t wd1  = (wpre + 16) ^ wsw;
    const int coff = (lane & 1) * 16;
    const int rowm = m0 + mg * 16 + (lane >> 1);

    const int rr = lane & 15;
    const uint32_t apre = (uint32_t)((rr >> 1) * 128 + (rr & 1) * 64 + (lane >> 4) * 16);
    const uint32_t asw  = ((uint32_t)(rr >> 1) & 7u) << 4;
    const uint32_t a_off[2] = { apre ^ asw, (apre + 32) ^ asw };

    auto issue_x = [&](int c) {
        const int t = c >> 2, s = c & 3;
        const __half* p = g_sigh + ((size_t)t * BATCH + rowm) * FEAT + s * 32 + coff;
        const uint32_t stg = awbase + (uint32_t)(c & 1) * 1024u;
        cp16(stg + wd0, p);
        cp16(stg + wd1, p + 8);
        CPA_COMMIT();
    };

    float acc[4][4];
    issue_x(0); issue_x(1);
    zero_acc(acc);
    const int NCH = 4 * T_STEPS;
    for (int c = 0; c < NCH; c++) {
        if (c + 1 < NCH) CPA_WAIT1(); else CPA_WAIT0();
        __syncwarp();
        const uint32_t stg = awbase + (uint32_t)(c & 1) * 1024u;
        mma_sub(stg, a_off, smu + GX_W, (c & 3) * 2, bo_sw, acc);
        if (c + 2 < NCH) issue_x(c + 2); else CPA_COMMIT();
        if ((c & 3) == 3) {
            const int t = c >> 2;
            uint4 v[2];
            __half2* hp = (__half2*)v;
            #pragma unroll
            for (int j = 0; j < 4; j++)
                #pragma unroll
                for (int r = 0; r < 4; r += 2)
                    hp[(j * 4 + r) >> 1] =
                        __floats2half2_rn(acc[j][r], acc[j][r + 1]);
            __half* dst = g_gx + ((size_t)(ct * T_STEPS + t) * NTHREADS + tid) * 16;
            *((uint4*)dst) = v[0];
            *((uint4*)(dst + 8)) = v[1];
            zero_acc(acc);
        }
    }
}

// ------------------------------ persistent kernel ----------------------------
__global__ void __launch_bounds__(NTHREADS, 1)
lstm_persistent(const float* __restrict__ Wlin, const float* __restrict__ blin,
                float* __restrict__ out) {
    extern __shared__ char smc[];
    const uint32_t smu = (uint32_t)__cvta_generic_to_shared(smc);
    const int tid = threadIdx.x, w = tid >> 5, lane = tid & 31;
    const int mg = w >> 1, nh = w & 1;       // 8 M-subgroups x 2 N-halves
    const int ct = blockIdx.x;
    const int mt = ct >> 5, nt = ct & 31;
    const int m0 = mt * MT, n0 = nt * NT, H0 = nt * 16;

    // ---- preload resident W1h (8 blocks: orig k-blocks 2..9) + W2 (16) ----
    {
        int row = tid >> 3, part = tid & 7;
        uint32_t o = (uint32_t)(row * 128 + part * 16);
        o ^= ((uint32_t)(row & 7)) << 4;
        const __half* s1 = g_Wp1h + (size_t)(n0 + row) * K1 + part * 8;
        for (int ckk = 0; ckk < W1_BLKS; ckk++)
            cp16(smu + SM_W1 + ckk * 8192 + o, s1 + (ckk + 2) * 64);
        const __half* s2 = g_Wp2h + (size_t)(n0 + row) * K2 + part * 8;
        for (int ckk = 0; ckk < W2_BLKS; ckk++)
            cp16(smu + SM_W2 + ckk * 8192 + o, s2 + ckk * 64);
        CPA_COMMIT();
        CPA_WAIT0();
        __syncthreads();
    }

    // ---- per-thread biases in registers (gate g, sub-col b) ----
    float b1r[4][2], b2r[4][2];
    #pragma unroll
    for (int g = 0; g < 4; g++)
        #pragma unroll
        for (int b = 0; b < 2; b++) {
            int c = n0 + nh * 32 + g * 8 + 2 * (lane & 3) + b;
            b1r[g][b] = g_b1[c];
            b2r[g][b] = g_b2[c];
        }

    // ---- swizzled LDSM offsets for B: this warp's two n16 blocks ----
    const uint32_t b_off0 = (uint32_t)(((((lane >> 4) & 1) * 8 + (lane & 7)) * 128)
                                       + ((lane >> 3) & 1) * 16);
    uint32_t bo_sw[2][4];
    #pragma unroll
    for (int p2 = 0; p2 < 2; p2++)
        #pragma unroll
        for (int kk = 0; kk < 4; kk++) {
            uint32_t bo = b_off0 + (uint32_t)((2 * nh + p2) * 2048 + kk * 32);
            bo ^= (bo >> 3) & 0x70u;
            bo_sw[p2][kk] = bo;
        }

    // ---- warp-private A stage: 2 slots x 1KB (R9 layout) ----
    const uint32_t awbase = smu + SM_AST + (uint32_t)w * 2048u;
    const uint32_t wpre = (uint32_t)((lane >> 2) * 128 + ((lane >> 1) & 1) * 64
                                     + (lane & 1) * 32);
    const uint32_t wsw  = ((uint32_t)(lane >> 2) & 7u) << 4;
    const uint32_t wd0  = wpre ^ wsw;
    const uint32_t wd1  = (wpre + 16) ^ wsw;
    const int coff = (lane & 1) * 16;                 // halves
    const int rowA = m0 + mg * 16 + (lane >> 1);

    const int rr = lane & 15;
    const uint32_t apre = (uint32_t)((rr >> 1) * 128 + (rr & 1) * 64 + (lane >> 4) * 16);
    const uint32_t asw  = ((uint32_t)(rr >> 1) & 7u) << 4;
    const uint32_t a_off[2] = { apre ^ asw, (apre + 32) ^ asw };

    const int base_row = m0 + mg * 16 + (lane >> 2);
    const int colb = H0 + nh * 8 + 2 * (lane & 3);

    float acc[4][4];
    unsigned round = 0;

    auto init_from_gx = [&](const uint4 gxv[2]) {
        const __half2* hp = (const __half2*)gxv;
        #pragma unroll
        for (int j = 0; j < 4; j++)
            #pragma unroll
            for (int r = 0; r < 4; r += 2) {
                float2 f2 = __half22float2(hp[(j * 4 + r) >> 1]);
                acc[j][r]     = f2.x;
                acc[j][r + 1] = f2.y;
            }
    };
    auto gx_ptr = [&](int t) {
        return (const uint4*)(g_gx + ((size_t)(ct * T_STEPS + t) * NTHREADS + tid) * 16);
    };
    auto preload_c = [&](const float* cbuf, float2 cv[2]) {
        #pragma unroll
        for (int rp = 0; rp < 2; rp++)
            cv[rp] = *(const float2*)(cbuf
                + (size_t)(base_row + rp * 8) * HID + colb);
    };

    // ---------------- prologue: A(0) = gx(0) + 0*W1h -> h1_0 in g_h1[1] ------
    {
        Src sa;
        sa.a0 = g_h1[0]; sa.lda0 = HID; sa.split = 16;    // zeros
        sa.a1 = g_h1[0]; sa.lda1 = HID;
        issue_sub(sa, 0, rowA, coff, awbase + wd0, awbase + wd1);
        issue_sub(sa, 1, rowA, coff, awbase + 1024u + wd0, awbase + 1024u + wd1);
        uint4 gxv[2];
        const uint4* gp = gx_ptr(0);
        gxv[0] = __ldcg(gp); gxv[1] = __ldcg(gp + 1);
        float2 cvA[2];
        preload_c(g_c1, cvA);
        init_from_gx(gxv);
        for (int j = 0; j < 16; j++) {
            if (j + 1 < 16) CPA_WAIT1(); else CPA_WAIT0();
            __syncwarp();
            const uint32_t stg = awbase + (uint32_t)(j & 1) * 1024u;
            mma_sub(stg, a_off, smu + SM_W1, j * 2, bo_sw, acc);
            if (j + 2 < 16) issue_sub(sa, j + 2, rowA, coff, stg + wd0, stg + wd1);
            else            CPA_COMMIT();
        }
        epilogue(acc, b1r, cvA, g_c1, g_h1[1], base_row, colb);
        group_sync(mt, ++round);
    }

    // ------------- steady state: region_t = [ B(t) ; A(t+1) ] ----------------
    for (int t = 0; t < T_STEPS; t++) {
        const int cur = (t + 1) & 1, prev = t & 1;
        Src sb;                               // B(t): [h1_t , h2_{t-1}]
        sb.a0 = g_h1[cur]; sb.lda0 = HID; sb.split = 16;
        sb.a1 = g_h2[prev]; sb.lda1 = HID;
        Src sa;                               // A(t+1): h1_t only (x via gx)
        sa.a0 = g_h1[cur]; sa.lda0 = HID; sa.split = 16;
        sa.a1 = g_h1[cur]; sa.lda1 = HID;
        const bool doA = (t + 1 < T_STEPS);

        // cold start (post-sync); overlap with out projection + c2 preload
        issue_sub(sb, 0, rowA, coff, awbase + wd0, awbase + wd1);
        issue_sub(sb, 1, rowA, coff, awbase + 1024u + wd0, awbase + 1024u + wd1);
        if (t > 0) out_calc(t - 1, g_h2[prev], Wlin, blin, out, ct);
        float2 cvB[2];
        preload_c(g_c2, cvB);

        // ---- B(t): 32 k32 chunks; tail issues A(t+1) chunks 0,1 ----
        zero_acc(acc);
        #pragma unroll 2
        for (int j = 0; j < 32; j++) {
            CPA_WAIT1();
            __syncwarp();
            const uint32_t stg = awbase + (uint32_t)(j & 1) * 1024u;
            mma_sub(stg, a_off, smu + SM_W2, j * 2, bo_sw, acc);
            if (j + 2 < 32)
                issue_sub(sb, j + 2, rowA, coff, stg + wd0, stg + wd1);
            else if (doA)
                issue_sub(sa, j - 30, rowA, coff, stg + wd0, stg + wd1);
            else
                CPA_COMMIT();
        }
        // preloads for A(t+1) — latency hidden under B epilogue MUFU work
        uint4 gxv[2];
        float2 cvA[2];
        if (doA) {
            const uint4* gp = gx_ptr(t + 1);
            gxv[0] = __ldcg(gp); gxv[1] = __ldcg(gp + 1);
            preload_c(g_c1, cvA);
        }
        epilogue(acc, b2r, cvB, g_c2, g_h2[cur], base_row, colb);

        // ---- A(t+1): 16 k32 chunks, acc preloaded with gx ----
        if (doA) {
            init_from_gx(gxv);
            #pragma unroll 2
            for (int j = 0; j < 16; j++) {
                if (j + 1 < 16) CPA_WAIT1(); else CPA_WAIT0();
                __syncwarp();
                const uint32_t stg = awbase + (uint32_t)(j & 1) * 1024u;
                mma_sub(stg, a_off, smu + SM_W1, j * 2, bo_sw, acc);
                if (j + 2 < 16) issue_sub(sa, j + 2, rowA, coff, stg + wd0, stg + wd1);
                else            CPA_COMMIT();
            }
            epilogue(acc, b1r, cvA, g_c1, g_h1[prev], base_row, colb);  // h1_{t+1}
        }
        group_sync(mt, ++round);
    }
    out_calc(T_STEPS - 1, g_h2[0], Wlin, blin, out, ct);
}

// --------------------------------- launcher ----------------------------------
extern "C" void kernel_launch(void* const* d_in, const int* in_sizes, int n_in,
                              void* d_out, int out_size) {
    const float* signal = (const float*)d_in[0];
    const float* Wih1   = (const float*)d_in[1];
    const float* Whh1   = (const float*)d_in[2];
    const float* bih1   = (const float*)d_in[3];
    const float* bhh1   = (const float*)d_in[4];
    const float* Wih2   = (const float*)d_in[5];
    const float* Whh2   = (const float*)d_in[6];
    const float* bih2   = (const float*)d_in[7];
    const float* bhh2   = (const float*)d_in[8];
    const float* Wlin   = (const float*)d_in[9];
    const float* blin   = (const float*)d_in[10];
    float* out = (float*)d_out;

    (void)in_sizes; (void)n_in; (void)out_size;

    cudaFuncSetAttribute(lstm_persistent,
                         cudaFuncAttributeMaxDynamicSharedMemorySize, SMEM_BYTES);
    cudaFuncSetAttribute(gemm_x_kernel,
                         cudaFuncAttributeMaxDynamicSharedMemorySize, GX_SMEM);

    prep_kernel<<<4096, 256>>>(signal, Wih1, Whh1, bih1, bhh1,
                               Wih2, Whh2, bih2, bhh2);
    gemm_x_kernel<<<NCTA, NTHREADS, GX_SMEM>>>();
    lstm_persistent<<<NCTA, NTHREADS, SMEM_BYTES>>>(Wlin, blin, out);
}